// round 15
// baseline (speedup 1.0000x reference)
#include <cuda_runtime.h>

// Fully fused UpFIRDn2d (crop -> bias -> up2 -> sep FIR12 -> leaky*sqrt2 -> sep FIR12 -> dn2)
// Tile: 32 rows x 64 cols of output per block; 512 threads; dynamic smem 65.5 KB.
// Polyphase up taps (pl=5 correlation):
//   y[2m]   = sum e[k]*x[m-3+k] (k=0..6)
//   y[2m+1] = sum o[k]*x[m-2+k] (k=0..5)
// Upsampled coords valid only on [0,256) per axis; outside -> 0 (dn-conv pad).
// Stage load-balance: S1 = 473 units single pass; S2 = 483 units single pass.
// S3/S4 packed fp32x2 FMA.
//
// SMEM regions (floats), aliased by lifetime:
//   A [0,10360):      s_x (43 x p78 = 3354) S0/S1;  a (74 x p140 = 10360) S2/S3
//   B [10360,16380):  t1 (43 x p140 = 6020) S1/S2;  t2 (74 x p68 = 5032) S3/S4
// Total 16380 floats = 65520 B -> 3 CTAs = 196.6 KB <= 228 KB.

#define NTHR 512
#define PX 78
#define PT 140
#define P2 68
#define RB_OFF 10360
#define SM_FLOATS 16380
#define SM_BYTES (SM_FLOATS * 4)

typedef unsigned long long u64;

__device__ __forceinline__ u64 pk2(float lo, float hi) {
    u64 r; asm("mov.b64 %0, {%1, %2};" : "=l"(r) : "f"(lo), "f"(hi)); return r;
}
__device__ __forceinline__ void upk2(u64 v, float& lo, float& hi) {
    asm("mov.b64 {%0, %1}, %2;" : "=f"(lo), "=f"(hi) : "l"(v));
}
__device__ __forceinline__ u64 ffma2(u64 a, u64 b, u64 c) {
    u64 d; asm("fma.rn.f32x2 %0, %1, %2, %3;" : "=l"(d) : "l"(a), "l"(b), "l"(c)); return d;
}

__global__ __launch_bounds__(NTHR, 3)
void upfirdn2d_fused_kernel(const float* __restrict__ x,
                            const float* __restrict__ bias,
                            const float* __restrict__ fup,
                            const float* __restrict__ fdn,
                            float* __restrict__ out)
{
    extern __shared__ float smem[];
    float* s_x  = smem;              // 43 x p78 (S0-S1)
    float* s_a  = smem;              // 74 x p140 (S2-S3), aliases s_x
    float* s_t1 = smem + RB_OFF;     // 43 x p140 (S1-S2)
    float* s_t2 = smem + RB_OFF;     // 74 x p68 (S3-S4), aliases t1

    const int tid  = threadIdx.x;
    const int lane = tid & 31;
    const int w    = tid >> 5;       // 0..15
    const int bc   = blockIdx.y;
    const int Y0   = (blockIdx.x >> 1) * 32;
    const int X0   = (blockIdx.x & 1) * 64;
    const bool y_int = (Y0 != 0) && (Y0 != 96);

    // polyphase up taps
    float e[7], o[6];
    {
        float up[12];
        #pragma unroll
        for (int k = 0; k < 12; k++) up[k] = fup[k];
        e[0] = up[0]; e[6] = up[11];
        #pragma unroll
        for (int j = 1; j < 6; j++) e[j] = up[2*j - 1] + up[2*j];
        #pragma unroll
        for (int j = 0; j < 6; j++) o[j] = up[2*j] + up[2*j + 1];
    }
    const float bv = bias[bc & 63];
    const float* xin = x + (size_t)bc * (130 * 130);

    // ---- S0: input rows + halo (cols 0..75), bias, zero pad (rows by warp) ----
    {
        const int r0    = (w < 11) ? 3 * w : 2 * w + 11;
        const int nrows = (w < 11) ? 3 : 2;
        #pragma unroll
        for (int rl = 0; rl < 3; rl++) {
            if (rl < nrows) {
                int r  = r0 + rl;
                int gy = Y0 - 5 + r;
                bool rowok = (unsigned)gy < 128u;
                const float* src = xin + (gy + 1) * 130 + (X0 - 5);
                float* dst = s_x + r * PX;
                #pragma unroll
                for (int ci = 0; ci < 3; ci++) {
                    int cc = lane + 32 * ci;
                    if (cc < 76) {
                        int gx = X0 - 6 + cc;
                        float v = 0.0f;
                        if (rowok && (unsigned)gx < 128u) v = src[cc] + bv;
                        dst[cc] = v;
                    }
                }
            }
        }
    }
    __syncthreads();

    // ---- S1: horizontal polyphase up -> t1[43][138]; 473 units, single pass ----
    // unit (r, tp 0..10): tp<10 -> pairs 6tp..6tp+5 (12 outputs);
    //                     tp=10 -> pairs 60..68 (18 outputs, chunked stores).
    if (tid < 473) {
        int r  = tid / 11;
        int tp = tid - r * 11;
        if (tp < 10) {
            const float2* row2 = reinterpret_cast<const float2*>(s_x + r * PX + 6 * tp);
            float xw[14];
            #pragma unroll
            for (int j = 0; j < 7; j++) {
                float2 q = row2[j];
                xw[2*j] = q.x; xw[2*j + 1] = q.y;
            }
            float res[12];
            #pragma unroll
            for (int p = 0; p < 6; p++) {
                float vo = o[0]*xw[p+1] + o[1]*xw[p+2] + o[2]*xw[p+3]
                         + o[3]*xw[p+4] + o[4]*xw[p+5] + o[5]*xw[p+6];
                float ve = e[0]*xw[p+1] + e[1]*xw[p+2] + e[2]*xw[p+3] + e[3]*xw[p+4]
                         + e[4]*xw[p+5] + e[5]*xw[p+6] + e[6]*xw[p+7];
                int gc = 2 * X0 - 5 + 12 * tp + 2 * p;
                res[2*p]     = ((unsigned)gc       < 256u) ? vo : 0.f;
                res[2*p + 1] = ((unsigned)(gc + 1) < 256u) ? ve : 0.f;
            }
            float* dst = s_t1 + r * PT + 12 * tp;
            *reinterpret_cast<float4*>(dst)     = make_float4(res[0],res[1],res[2],res[3]);
            *reinterpret_cast<float4*>(dst + 4) = make_float4(res[4],res[5],res[6],res[7]);
            *reinterpret_cast<float4*>(dst + 8) = make_float4(res[8],res[9],res[10],res[11]);
        } else {
            // pairs 60..68, window x cols 60..75 (8 float2)
            const float2* row2 = reinterpret_cast<const float2*>(s_x + r * PX + 60);
            float xw[16];
            #pragma unroll
            for (int j = 0; j < 8; j++) {
                float2 q = row2[j];
                xw[2*j] = q.x; xw[2*j + 1] = q.y;
            }
            float* dst = s_t1 + r * PT + 120;
            // 3 chunks of 3 pairs to cap live registers
            #pragma unroll
            for (int ch = 0; ch < 3; ch++) {
                float res[6];
                #pragma unroll
                for (int pp = 0; pp < 3; pp++) {
                    int p = 3 * ch + pp;   // local pair 0..8
                    float vo = o[0]*xw[p+1] + o[1]*xw[p+2] + o[2]*xw[p+3]
                             + o[3]*xw[p+4] + o[4]*xw[p+5] + o[5]*xw[p+6];
                    float ve = e[0]*xw[p+1] + e[1]*xw[p+2] + e[2]*xw[p+3] + e[3]*xw[p+4]
                             + e[4]*xw[p+5] + e[5]*xw[p+6] + e[6]*xw[p+7];
                    int gc = 2 * X0 - 5 + 120 + 2 * p;
                    res[2*pp]     = ((unsigned)gc       < 256u) ? vo : 0.f;
                    res[2*pp + 1] = ((unsigned)(gc + 1) < 256u) ? ve : 0.f;
                }
                float* d2 = dst + 6 * ch;
                if (ch == 0) {
                    *reinterpret_cast<float4*>(d2)     = make_float4(res[0],res[1],res[2],res[3]);
                    *reinterpret_cast<float2*>(d2 + 4) = make_float2(res[4],res[5]);
                } else if (ch == 1) {
                    *reinterpret_cast<float2*>(d2)     = make_float2(res[0],res[1]);
                    *reinterpret_cast<float4*>(d2 + 2) = make_float4(res[2],res[3],res[4],res[5]);
                } else {
                    *reinterpret_cast<float4*>(d2)     = make_float4(res[0],res[1],res[2],res[3]);
                    *reinterpret_cast<float2*>(d2 + 4) = make_float2(res[4],res[5]);
                }
            }
        }
    }

    // fold leaky gain sqrt(2) into up taps (sign test invariant under positive scale)
    {
        const float G = 1.41421356237309515f;
        #pragma unroll
        for (int k = 0; k < 7; k++) e[k] *= G;
        #pragma unroll
        for (int k = 0; k < 6; k++) o[k] *= G;
    }
    __syncthreads();

    // ---- S2: vertical polyphase up + leaky -> a[74][138]; 483 units, single pass ----
    // u < 414: unit (g = u/69, ac2 = u%69): row-pairs i = 6g..6g+5, ring window
    //          over t1 rows 6g..6g+11 (all i <= 35, no guard).
    // 414 <= u < 483: row-pair 36, ac2 = u-414 (7-row window, 2 output rows).
    if (tid < 483) {
        if (tid < 414) {
            int g   = tid / 69;
            int ac2 = tid - g * 69;
            const float* base = s_t1 + (6 * g) * PT + 2 * ac2;
            float2 wv[7];
            #pragma unroll
            for (int j = 0; j < 7; j++)
                wv[j] = *reinterpret_cast<const float2*>(base + j * PT);
            float* adst = s_a + (12 * g) * PT + 2 * ac2;
            #pragma unroll
            for (int p = 0; p < 6; p++) {
                int i = 6 * g + p;
                float vox = o[0]*wv[(p)%7].x   + o[1]*wv[(p+1)%7].x + o[2]*wv[(p+2)%7].x
                          + o[3]*wv[(p+3)%7].x + o[4]*wv[(p+4)%7].x + o[5]*wv[(p+5)%7].x;
                float voy = o[0]*wv[(p)%7].y   + o[1]*wv[(p+1)%7].y + o[2]*wv[(p+2)%7].y
                          + o[3]*wv[(p+3)%7].y + o[4]*wv[(p+4)%7].y + o[5]*wv[(p+5)%7].y;
                float vex = e[0]*wv[(p)%7].x   + e[1]*wv[(p+1)%7].x + e[2]*wv[(p+2)%7].x
                          + e[3]*wv[(p+3)%7].x + e[4]*wv[(p+4)%7].x + e[5]*wv[(p+5)%7].x
                          + e[6]*wv[(p+6)%7].x;
                float vey = e[0]*wv[(p)%7].y   + e[1]*wv[(p+1)%7].y + e[2]*wv[(p+2)%7].y
                          + e[3]*wv[(p+3)%7].y + e[4]*wv[(p+4)%7].y + e[5]*wv[(p+5)%7].y
                          + e[6]*wv[(p+6)%7].y;
                if (!y_int) {
                    int gr = 2 * Y0 - 5 + 2 * i;
                    bool ok0 = (unsigned)gr       < 256u;
                    bool ok1 = (unsigned)(gr + 1) < 256u;
                    vox = ok0 ? vox : 0.f;  voy = ok0 ? voy : 0.f;
                    vex = ok1 ? vex : 0.f;  vey = ok1 ? vey : 0.f;
                }
                float2 ro, re;
                ro.x = (vox >= 0.f) ? vox : 0.2f * vox;
                ro.y = (voy >= 0.f) ? voy : 0.2f * voy;
                re.x = (vex >= 0.f) ? vex : 0.2f * vex;
                re.y = (vey >= 0.f) ? vey : 0.2f * vey;
                *reinterpret_cast<float2*>(adst + (2 * p)     * PT) = ro;
                *reinterpret_cast<float2*>(adst + (2 * p + 1) * PT) = re;
                if (p < 5)
                    wv[p % 7] = *reinterpret_cast<const float2*>(base + (p + 7) * PT);
            }
        } else {
            int ac2 = tid - 414;
            const float* base = s_t1 + 36 * PT + 2 * ac2;
            float2 wv[7];
            #pragma unroll
            for (int j = 0; j < 7; j++)
                wv[j] = *reinterpret_cast<const float2*>(base + j * PT);
            float vox = o[0]*wv[0].x + o[1]*wv[1].x + o[2]*wv[2].x
                      + o[3]*wv[3].x + o[4]*wv[4].x + o[5]*wv[5].x;
            float voy = o[0]*wv[0].y + o[1]*wv[1].y + o[2]*wv[2].y
                      + o[3]*wv[3].y + o[4]*wv[4].y + o[5]*wv[5].y;
            float vex = e[0]*wv[0].x + e[1]*wv[1].x + e[2]*wv[2].x + e[3]*wv[3].x
                      + e[4]*wv[4].x + e[5]*wv[5].x + e[6]*wv[6].x;
            float vey = e[0]*wv[0].y + e[1]*wv[1].y + e[2]*wv[2].y + e[3]*wv[3].y
                      + e[4]*wv[4].y + e[5]*wv[5].y + e[6]*wv[6].y;
            if (!y_int) {
                int gr = 2 * Y0 - 5 + 72;
                bool ok0 = (unsigned)gr       < 256u;
                bool ok1 = (unsigned)(gr + 1) < 256u;
                vox = ok0 ? vox : 0.f;  voy = ok0 ? voy : 0.f;
                vex = ok1 ? vex : 0.f;  vey = ok1 ? vey : 0.f;
            }
            float2 ro, re;
            ro.x = (vox >= 0.f) ? vox : 0.2f * vox;
            ro.y = (voy >= 0.f) ? voy : 0.2f * voy;
            re.x = (vex >= 0.f) ? vex : 0.2f * vex;
            re.y = (vey >= 0.f) ? vey : 0.2f * vey;
            float* adst = s_a + 72 * PT + 2 * ac2;
            *reinterpret_cast<float2*>(adst)      = ro;
            *reinterpret_cast<float2*>(adst + PT) = re;
        }
    }
    __syncthreads();

    // dn taps as packed pairs: pdn[m] = (dn[2m], dn[2m+1])
    u64 pdn[6];
    #pragma unroll
    for (int m = 0; m < 6; m++) pdn[m] = pk2(fdn[2*m], fdn[2*m + 1]);

    // ---- S3: horizontal dn-conv, stride-2 -> t2[74][64]; packed f32x2 ----
    #pragma unroll
    for (int it = 0; it < 2; it++) {
        int u = tid + 512 * it;
        if (u < 8 * 74) {
            int t  = u / 74;
            int ar = u - t * 74;
            const float4* row = reinterpret_cast<const float4*>(s_a + ar * PT + 16 * t);
            u64 facc[8] = {0,0,0,0,0,0,0,0};
            #pragma unroll
            for (int j = 0; j < 7; j++) {
                float4 qv = row[j];
                u64 pelA = pk2(qv.x, qv.y);
                u64 pelB = pk2(qv.z, qv.w);
                const int nA = 2 * j, nB = 2 * j + 1;
                #pragma unroll
                for (int q = 0; q < 8; q++) {
                    int mA = nA - q;
                    if (mA >= 0 && mA < 6) facc[q] = ffma2(pdn[mA], pelA, facc[q]);
                    int mB = nB - q;
                    if (mB >= 0 && mB < 6) facc[q] = ffma2(pdn[mB], pelB, facc[q]);
                }
            }
            float acc[8];
            #pragma unroll
            for (int q = 0; q < 8; q++) {
                float lo, hi; upk2(facc[q], lo, hi);
                acc[q] = lo + hi;
            }
            float* dst = s_t2 + ar * P2 + 8 * t;
            *reinterpret_cast<float4*>(dst)     = make_float4(acc[0],acc[1],acc[2],acc[3]);
            *reinterpret_cast<float4*>(dst + 4) = make_float4(acc[4],acc[5],acc[6],acc[7]);
        }
    }
    __syncthreads();

    // ---- S4: vertical dn-conv, stride-2 -> out; packed f32x2, streamed loads ----
    if (tid < 256) {
        int cp = tid & 31;
        int yg = tid >> 5;
        u64 d2[12];
        #pragma unroll
        for (int m = 0; m < 6; m++) {
            float a_, b_; upk2(pdn[m], a_, b_);
            d2[2*m]     = pk2(a_, a_);
            d2[2*m + 1] = pk2(b_, b_);
        }
        const float* base = s_t2 + (8 * yg) * P2 + 2 * cp;
        u64 facc[4] = {0,0,0,0};
        #pragma unroll
        for (int j = 0; j < 18; j++) {
            u64 r = *reinterpret_cast<const u64*>(base + j * P2);
            #pragma unroll
            for (int q = 0; q < 4; q++) {
                const int k = j - 2 * q;
                if (k >= 0 && k < 12) facc[q] = ffma2(d2[k], r, facc[q]);
            }
        }
        float* op = out + ((size_t)bc * 128 + (Y0 + 4 * yg)) * 128 + X0 + 2 * cp;
        #pragma unroll
        for (int q = 0; q < 4; q++)
            *reinterpret_cast<u64*>(op + q * 128) = facc[q];
    }
}

extern "C" void kernel_launch(void* const* d_in, const int* in_sizes, int n_in,
                              void* d_out, int out_size)
{
    const float* x    = (const float*)d_in[0];   // (8,64,130,130) fp32
    const float* bias = (const float*)d_in[1];   // (64,) fp32
    const float* fup  = (const float*)d_in[2];   // (12,) fp32
    const float* fdn  = (const float*)d_in[3];   // (12,) fp32
    float* out = (float*)d_out;                  // (8,64,128,128) fp32

    // capture-safe (not a stream op); idempotent, called every launch
    cudaFuncSetAttribute(upfirdn2d_fused_kernel,
                         cudaFuncAttributeMaxDynamicSharedMemorySize, SM_BYTES);

    dim3 grid(8, 512);   // 8 tiles (2 wide x 4 tall) per channel-image
    upfirdn2d_fused_kernel<<<grid, NTHR, SM_BYTES>>>(x, bias, fup, fdn, out);
}

// round 16
// speedup vs baseline: 1.1703x; 1.1703x over previous
#include <cuda_runtime.h>

// Fully fused UpFIRDn2d (crop -> bias -> up2 -> sep FIR12 -> leaky*sqrt2 -> sep FIR12 -> dn2)
// Tile: 32 rows x 64 cols of output per block; 512 threads; dynamic smem 65.5 KB.
// Polyphase up taps (pl=5 correlation):
//   y[2m]   = sum e[k]*x[m-3+k] (k=0..6)
//   y[2m+1] = sum o[k]*x[m-2+k] (k=0..5)
// Upsampled coords valid only on [0,256) per axis; outside -> 0 (dn-conv pad).
// Load balance is WARP-SEGREGATED: S1 main units (6 pairs) on warps 0-13, tail
// units (9 pairs) on warps 14-15; S2 main (6 row-pairs) on warps 0-12, tail
// (1 row-pair) on warps 13-15. No warp executes two unit types.
// S3/S4 packed fp32x2 FMA.
//
// SMEM regions (floats), aliased by lifetime:
//   A [0,10360):      s_x (43 x p78 = 3354) S0/S1;  a (74 x p140 = 10360) S2/S3
//   B [10360,16380):  t1 (43 x p140 = 6020) S1/S2;  t2 (74 x p68 = 5032) S3/S4
// Total 16380 floats = 65520 B -> 3 CTAs = 196.6 KB <= 228 KB.

#define NTHR 512
#define PX 78
#define PT 140
#define P2 68
#define RB_OFF 10360
#define SM_FLOATS 16380
#define SM_BYTES (SM_FLOATS * 4)

typedef unsigned long long u64;

__device__ __forceinline__ u64 pk2(float lo, float hi) {
    u64 r; asm("mov.b64 %0, {%1, %2};" : "=l"(r) : "f"(lo), "f"(hi)); return r;
}
__device__ __forceinline__ void upk2(u64 v, float& lo, float& hi) {
    asm("mov.b64 {%0, %1}, %2;" : "=f"(lo), "=f"(hi) : "l"(v));
}
__device__ __forceinline__ u64 ffma2(u64 a, u64 b, u64 c) {
    u64 d; asm("fma.rn.f32x2 %0, %1, %2, %3;" : "=l"(d) : "l"(a), "l"(b), "l"(c)); return d;
}

__global__ __launch_bounds__(NTHR, 3)
void upfirdn2d_fused_kernel(const float* __restrict__ x,
                            const float* __restrict__ bias,
                            const float* __restrict__ fup,
                            const float* __restrict__ fdn,
                            float* __restrict__ out)
{
    extern __shared__ float smem[];
    float* s_x  = smem;              // 43 x p78 (S0-S1)
    float* s_a  = smem;              // 74 x p140 (S2-S3), aliases s_x
    float* s_t1 = smem + RB_OFF;     // 43 x p140 (S1-S2)
    float* s_t2 = smem + RB_OFF;     // 74 x p68 (S3-S4), aliases t1

    const int tid  = threadIdx.x;
    const int lane = tid & 31;
    const int w    = tid >> 5;       // 0..15
    const int bc   = blockIdx.y;
    const int Y0   = (blockIdx.x >> 1) * 32;
    const int X0   = (blockIdx.x & 1) * 64;
    const bool y_int = (Y0 != 0) && (Y0 != 96);

    // polyphase up taps
    float e[7], o[6];
    {
        float up[12];
        #pragma unroll
        for (int k = 0; k < 12; k++) up[k] = fup[k];
        e[0] = up[0]; e[6] = up[11];
        #pragma unroll
        for (int j = 1; j < 6; j++) e[j] = up[2*j - 1] + up[2*j];
        #pragma unroll
        for (int j = 0; j < 6; j++) o[j] = up[2*j] + up[2*j + 1];
    }
    const float bv = bias[bc & 63];
    const float* xin = x + (size_t)bc * (130 * 130);

    // ---- S0: input rows + halo (cols 0..75), bias, zero pad (rows by warp) ----
    {
        const int r0    = (w < 11) ? 3 * w : 2 * w + 11;
        const int nrows = (w < 11) ? 3 : 2;
        #pragma unroll
        for (int rl = 0; rl < 3; rl++) {
            if (rl < nrows) {
                int r  = r0 + rl;
                int gy = Y0 - 5 + r;
                bool rowok = (unsigned)gy < 128u;
                const float* src = xin + (gy + 1) * 130 + (X0 - 5);
                float* dst = s_x + r * PX;
                #pragma unroll
                for (int ci = 0; ci < 3; ci++) {
                    int cc = lane + 32 * ci;
                    if (cc < 76) {
                        int gx = X0 - 6 + cc;
                        float v = 0.0f;
                        if (rowok && (unsigned)gx < 128u) v = src[cc] + bv;
                        dst[cc] = v;
                    }
                }
            }
        }
    }
    __syncthreads();

    // ---- S1: horizontal polyphase up -> t1[43][138]; warp-segregated units ----
    // Main (tid < 430, warps 0-13): tp = tid/43 in 0..9, r = tid%43;
    //   pairs 6tp..6tp+5, window x cols 6tp..6tp+13 (7 float2).
    // Tail (448 <= tid < 491, warps 14-15): r = tid-448; pairs 60..68 (9 pairs).
    if (tid < 430) {
        int tp = tid / 43;
        int r  = tid - tp * 43;
        const float2* row2 = reinterpret_cast<const float2*>(s_x + r * PX + 6 * tp);
        float xw[14];
        #pragma unroll
        for (int j = 0; j < 7; j++) {
            float2 q = row2[j];
            xw[2*j] = q.x; xw[2*j + 1] = q.y;
        }
        float res[12];
        #pragma unroll
        for (int p = 0; p < 6; p++) {
            float vo = o[0]*xw[p+1] + o[1]*xw[p+2] + o[2]*xw[p+3]
                     + o[3]*xw[p+4] + o[4]*xw[p+5] + o[5]*xw[p+6];
            float ve = e[0]*xw[p+1] + e[1]*xw[p+2] + e[2]*xw[p+3] + e[3]*xw[p+4]
                     + e[4]*xw[p+5] + e[5]*xw[p+6] + e[6]*xw[p+7];
            int gc = 2 * X0 - 5 + 12 * tp + 2 * p;
            res[2*p]     = ((unsigned)gc       < 256u) ? vo : 0.f;
            res[2*p + 1] = ((unsigned)(gc + 1) < 256u) ? ve : 0.f;
        }
        float* dst = s_t1 + r * PT + 12 * tp;
        *reinterpret_cast<float4*>(dst)     = make_float4(res[0],res[1],res[2],res[3]);
        *reinterpret_cast<float4*>(dst + 4) = make_float4(res[4],res[5],res[6],res[7]);
        *reinterpret_cast<float4*>(dst + 8) = make_float4(res[8],res[9],res[10],res[11]);
    } else if (tid >= 448 && tid < 491) {
        int r = tid - 448;
        // pairs 60..68, window x cols 60..75 (8 float2)
        const float2* row2 = reinterpret_cast<const float2*>(s_x + r * PX + 60);
        float xw[16];
        #pragma unroll
        for (int j = 0; j < 8; j++) {
            float2 q = row2[j];
            xw[2*j] = q.x; xw[2*j + 1] = q.y;
        }
        float* dst = s_t1 + r * PT + 120;
        #pragma unroll
        for (int ch = 0; ch < 3; ch++) {
            float res[6];
            #pragma unroll
            for (int pp = 0; pp < 3; pp++) {
                int p = 3 * ch + pp;   // local pair 0..8
                float vo = o[0]*xw[p+1] + o[1]*xw[p+2] + o[2]*xw[p+3]
                         + o[3]*xw[p+4] + o[4]*xw[p+5] + o[5]*xw[p+6];
                float ve = e[0]*xw[p+1] + e[1]*xw[p+2] + e[2]*xw[p+3] + e[3]*xw[p+4]
                         + e[4]*xw[p+5] + e[5]*xw[p+6] + e[6]*xw[p+7];
                int gc = 2 * X0 - 5 + 120 + 2 * p;
                res[2*pp]     = ((unsigned)gc       < 256u) ? vo : 0.f;
                res[2*pp + 1] = ((unsigned)(gc + 1) < 256u) ? ve : 0.f;
            }
            float* d2 = dst + 6 * ch;
            if (ch == 1) {
                *reinterpret_cast<float2*>(d2)     = make_float2(res[0],res[1]);
                *reinterpret_cast<float4*>(d2 + 2) = make_float4(res[2],res[3],res[4],res[5]);
            } else {
                *reinterpret_cast<float4*>(d2)     = make_float4(res[0],res[1],res[2],res[3]);
                *reinterpret_cast<float2*>(d2 + 4) = make_float2(res[4],res[5]);
            }
        }
    }

    // fold leaky gain sqrt(2) into up taps (sign test invariant under positive scale)
    {
        const float G = 1.41421356237309515f;
        #pragma unroll
        for (int k = 0; k < 7; k++) e[k] *= G;
        #pragma unroll
        for (int k = 0; k < 6; k++) o[k] *= G;
    }
    __syncthreads();

    // ---- S2: vertical polyphase up + leaky -> a[74][138]; warp-segregated ----
    // Main (tid < 414, warps 0-12): g = tid/69 in 0..5, ac2 = tid%69;
    //   row-pairs i = 6g..6g+5 (all <= 35), ring window over t1 rows 6g..6g+11.
    // Tail (416 <= tid < 485, warps 13-15): ac2 = tid-416; row-pair 36.
    if (tid < 414) {
        int g   = tid / 69;
        int ac2 = tid - g * 69;
        const float* base = s_t1 + (6 * g) * PT + 2 * ac2;
        float2 wv[7];
        #pragma unroll
        for (int j = 0; j < 7; j++)
            wv[j] = *reinterpret_cast<const float2*>(base + j * PT);
        float* adst = s_a + (12 * g) * PT + 2 * ac2;
        #pragma unroll
        for (int p = 0; p < 6; p++) {
            int i = 6 * g + p;
            float vox = o[0]*wv[(p)%7].x   + o[1]*wv[(p+1)%7].x + o[2]*wv[(p+2)%7].x
                      + o[3]*wv[(p+3)%7].x + o[4]*wv[(p+4)%7].x + o[5]*wv[(p+5)%7].x;
            float voy = o[0]*wv[(p)%7].y   + o[1]*wv[(p+1)%7].y + o[2]*wv[(p+2)%7].y
                      + o[3]*wv[(p+3)%7].y + o[4]*wv[(p+4)%7].y + o[5]*wv[(p+5)%7].y;
            float vex = e[0]*wv[(p)%7].x   + e[1]*wv[(p+1)%7].x + e[2]*wv[(p+2)%7].x
                      + e[3]*wv[(p+3)%7].x + e[4]*wv[(p+4)%7].x + e[5]*wv[(p+5)%7].x
                      + e[6]*wv[(p+6)%7].x;
            float vey = e[0]*wv[(p)%7].y   + e[1]*wv[(p+1)%7].y + e[2]*wv[(p+2)%7].y
                      + e[3]*wv[(p+3)%7].y + e[4]*wv[(p+4)%7].y + e[5]*wv[(p+5)%7].y
                      + e[6]*wv[(p+6)%7].y;
            if (!y_int) {
                int gr = 2 * Y0 - 5 + 2 * i;
                bool ok0 = (unsigned)gr       < 256u;
                bool ok1 = (unsigned)(gr + 1) < 256u;
                vox = ok0 ? vox : 0.f;  voy = ok0 ? voy : 0.f;
                vex = ok1 ? vex : 0.f;  vey = ok1 ? vey : 0.f;
            }
            float2 ro, re;
            ro.x = (vox >= 0.f) ? vox : 0.2f * vox;
            ro.y = (voy >= 0.f) ? voy : 0.2f * voy;
            re.x = (vex >= 0.f) ? vex : 0.2f * vex;
            re.y = (vey >= 0.f) ? vey : 0.2f * vey;
            *reinterpret_cast<float2*>(adst + (2 * p)     * PT) = ro;
            *reinterpret_cast<float2*>(adst + (2 * p + 1) * PT) = re;
            if (p < 5)
                wv[p % 7] = *reinterpret_cast<const float2*>(base + (p + 7) * PT);
        }
    } else if (tid >= 416 && tid < 485) {
        int ac2 = tid - 416;
        const float* base = s_t1 + 36 * PT + 2 * ac2;
        float2 wv[7];
        #pragma unroll
        for (int j = 0; j < 7; j++)
            wv[j] = *reinterpret_cast<const float2*>(base + j * PT);
        float vox = o[0]*wv[0].x + o[1]*wv[1].x + o[2]*wv[2].x
                  + o[3]*wv[3].x + o[4]*wv[4].x + o[5]*wv[5].x;
        float voy = o[0]*wv[0].y + o[1]*wv[1].y + o[2]*wv[2].y
                  + o[3]*wv[3].y + o[4]*wv[4].y + o[5]*wv[5].y;
        float vex = e[0]*wv[0].x + e[1]*wv[1].x + e[2]*wv[2].x + e[3]*wv[3].x
                  + e[4]*wv[4].x + e[5]*wv[5].x + e[6]*wv[6].x;
        float vey = e[0]*wv[0].y + e[1]*wv[1].y + e[2]*wv[2].y + e[3]*wv[3].y
                  + e[4]*wv[4].y + e[5]*wv[5].y + e[6]*wv[6].y;
        if (!y_int) {
            int gr = 2 * Y0 - 5 + 72;
            bool ok0 = (unsigned)gr       < 256u;
            bool ok1 = (unsigned)(gr + 1) < 256u;
            vox = ok0 ? vox : 0.f;  voy = ok0 ? voy : 0.f;
            vex = ok1 ? vex : 0.f;  vey = ok1 ? vey : 0.f;
        }
        float2 ro, re;
        ro.x = (vox >= 0.f) ? vox : 0.2f * vox;
        ro.y = (voy >= 0.f) ? voy : 0.2f * voy;
        re.x = (vex >= 0.f) ? vex : 0.2f * vex;
        re.y = (vey >= 0.f) ? vey : 0.2f * vey;
        float* adst = s_a + 72 * PT + 2 * ac2;
        *reinterpret_cast<float2*>(adst)      = ro;
        *reinterpret_cast<float2*>(adst + PT) = re;
    }
    __syncthreads();

    // dn taps as packed pairs: pdn[m] = (dn[2m], dn[2m+1])
    u64 pdn[6];
    #pragma unroll
    for (int m = 0; m < 6; m++) pdn[m] = pk2(fdn[2*m], fdn[2*m + 1]);

    // ---- S3: horizontal dn-conv, stride-2 -> t2[74][64]; packed f32x2 ----
    #pragma unroll
    for (int it = 0; it < 2; it++) {
        int u = tid + 512 * it;
        if (u < 8 * 74) {
            int t  = u / 74;
            int ar = u - t * 74;
            const float4* row = reinterpret_cast<const float4*>(s_a + ar * PT + 16 * t);
            u64 facc[8] = {0,0,0,0,0,0,0,0};
            #pragma unroll
            for (int j = 0; j < 7; j++) {
                float4 qv = row[j];
                u64 pelA = pk2(qv.x, qv.y);
                u64 pelB = pk2(qv.z, qv.w);
                const int nA = 2 * j, nB = 2 * j + 1;
                #pragma unroll
                for (int q = 0; q < 8; q++) {
                    int mA = nA - q;
                    if (mA >= 0 && mA < 6) facc[q] = ffma2(pdn[mA], pelA, facc[q]);
                    int mB = nB - q;
                    if (mB >= 0 && mB < 6) facc[q] = ffma2(pdn[mB], pelB, facc[q]);
                }
            }
            float acc[8];
            #pragma unroll
            for (int q = 0; q < 8; q++) {
                float lo, hi; upk2(facc[q], lo, hi);
                acc[q] = lo + hi;
            }
            float* dst = s_t2 + ar * P2 + 8 * t;
            *reinterpret_cast<float4*>(dst)     = make_float4(acc[0],acc[1],acc[2],acc[3]);
            *reinterpret_cast<float4*>(dst + 4) = make_float4(acc[4],acc[5],acc[6],acc[7]);
        }
    }
    __syncthreads();

    // ---- S4: vertical dn-conv, stride-2 -> out; packed f32x2, streamed loads ----
    if (tid < 256) {
        int cp = tid & 31;
        int yg = tid >> 5;
        u64 d2[12];
        #pragma unroll
        for (int m = 0; m < 6; m++) {
            float a_, b_; upk2(pdn[m], a_, b_);
            d2[2*m]     = pk2(a_, a_);
            d2[2*m + 1] = pk2(b_, b_);
        }
        const float* base = s_t2 + (8 * yg) * P2 + 2 * cp;
        u64 facc[4] = {0,0,0,0};
        #pragma unroll
        for (int j = 0; j < 18; j++) {
            u64 r = *reinterpret_cast<const u64*>(base + j * P2);
            #pragma unroll
            for (int q = 0; q < 4; q++) {
                const int k = j - 2 * q;
                if (k >= 0 && k < 12) facc[q] = ffma2(d2[k], r, facc[q]);
            }
        }
        float* op = out + ((size_t)bc * 128 + (Y0 + 4 * yg)) * 128 + X0 + 2 * cp;
        #pragma unroll
        for (int q = 0; q < 4; q++)
            *reinterpret_cast<u64*>(op + q * 128) = facc[q];
    }
}

extern "C" void kernel_launch(void* const* d_in, const int* in_sizes, int n_in,
                              void* d_out, int out_size)
{
    const float* x    = (const float*)d_in[0];   // (8,64,130,130) fp32
    const float* bias = (const float*)d_in[1];   // (64,) fp32
    const float* fup  = (const float*)d_in[2];   // (12,) fp32
    const float* fdn  = (const float*)d_in[3];   // (12,) fp32
    float* out = (float*)d_out;                  // (8,64,128,128) fp32

    // capture-safe (not a stream op); idempotent, called every launch
    cudaFuncSetAttribute(upfirdn2d_fused_kernel,
                         cudaFuncAttributeMaxDynamicSharedMemorySize, SM_BYTES);

    dim3 grid(8, 512);   // 8 tiles (2 wide x 4 tall) per channel-image
    upfirdn2d_fused_kernel<<<grid, NTHR, SM_BYTES>>>(x, bias, fup, fdn, out);
}